// round 10
// baseline (speedup 1.0000x reference)
#include <cuda_runtime.h>
#include <cuda_bf16.h>
#include <cstdint>

#define BATCH 2
#define SEQ   2048
#define DM    1024
#define NH    16
#define DH    64
#define KS    32

#define MROWS (BATCH*SEQ)   // 4096
#define FULLM 0xffffffffu
#define NTRI  136

// ---------------- scratch ----------------------------------------------------
__device__ float g_Q [BATCH*SEQ*DM];
__device__ float g_K [BATCH*SEQ*DM];
__device__ float g_V [BATCH*SEQ*DM];
__device__ float g_HO[BATCH*SEQ*DM];
__device__ float g_WGT[BATCH*NH*SEQ*KS];
__device__ int   g_IDX[BATCH*NH*SEQ*KS];
__device__ float g_SC[(size_t)BATCH*NH*SEQ*SEQ];

__device__ __forceinline__ float neg_inf() { return __int_as_float(0xff800000); }

// ---------------- tf32 helpers -----------------------------------------------
__device__ __forceinline__ uint32_t f2tf32(float x) {
    uint32_t r; asm("cvt.rna.tf32.f32 %0, %1;" : "=r"(r) : "f"(x)); return r;
}

// d = a*b + c  (in-place accumulate)
__device__ __forceinline__ void mma_tf32(float* c,
    uint32_t a0, uint32_t a1, uint32_t a2, uint32_t a3,
    uint32_t b0, uint32_t b1)
{
    asm volatile(
        "mma.sync.aligned.m16n8k8.row.col.f32.tf32.tf32.f32 "
        "{%0,%1,%2,%3}, {%4,%5,%6,%7}, {%8,%9}, {%0,%1,%2,%3};"
        : "+f"(c[0]), "+f"(c[1]), "+f"(c[2]), "+f"(c[3])
        : "r"(a0), "r"(a1), "r"(a2), "r"(a3), "r"(b0), "r"(b1));
}

// d = a*b + 0   (fresh chunk accumulator, explicit zero C)
__device__ __forceinline__ void mma_tf32_zc(float* d,
    uint32_t a0, uint32_t a1, uint32_t a2, uint32_t a3,
    uint32_t b0, uint32_t b1)
{
    asm volatile(
        "mma.sync.aligned.m16n8k8.row.col.f32.tf32.tf32.f32 "
        "{%0,%1,%2,%3}, {%4,%5,%6,%7}, {%8,%9}, {%10,%11,%12,%13};"
        : "=f"(d[0]), "=f"(d[1]), "=f"(d[2]), "=f"(d[3])
        : "r"(a0), "r"(a1), "r"(a2), "r"(a3), "r"(b0), "r"(b1),
          "f"(0.f), "f"(0.f), "f"(0.f), "f"(0.f));
}

// ---------------- core: 128x128 tile, C = scale*(A@B^T) + bias ---------------
// smem word layout per row (BK=16): two k8 groups; within group g, logical
// col c (0..7) stored at word g*8 + (c&3)*2 + (c>>2) so that (c, c+4) are
// adjacent -> fragment pair = one LDS.64.
#define BKT 16
#define RS  18   // row stride in words

__device__ __forceinline__ void store_hilo_tf32(
    uint32_t* H, uint32_t* L, int row, int f4, float4 v)
{
    uint32_t hx = f2tf32(v.x), hy = f2tf32(v.y), hz = f2tf32(v.z), hw = f2tf32(v.w);
    uint32_t lx = f2tf32(v.x - __uint_as_float(hx));
    uint32_t ly = f2tf32(v.y - __uint_as_float(hy));
    uint32_t lz = f2tf32(v.z - __uint_as_float(hz));
    uint32_t lw = f2tf32(v.w - __uint_as_float(hw));
    int g = f4 >> 1;
    int base = row * RS + g * 8 + (f4 & 1);
    H[base + 0] = hx; H[base + 2] = hy; H[base + 4] = hz; H[base + 6] = hw;
    L[base + 0] = lx; L[base + 2] = ly; L[base + 4] = lz; L[base + 6] = lw;
}

__device__ __forceinline__ void gemm_tile_tf32(
    const float* __restrict__ A, int lda,
    const float* __restrict__ B, int ldb,
    int Kdim,
    float* __restrict__ C, int ldc,
    const float* __restrict__ bias, float scale)
{
    __shared__ __align__(16) uint32_t AsH[128 * RS];
    __shared__ __align__(16) uint32_t AsL[128 * RS];
    __shared__ __align__(16) uint32_t BsH[128 * RS];
    __shared__ __align__(16) uint32_t BsL[128 * RS];

    const int tid  = threadIdx.x;
    const int lane = tid & 31, w = tid >> 5;
    const int wm = w >> 2, wn = w & 3;          // 2 x 4 warp grid
    const int lr = lane >> 2, lc = lane & 3;

    float acc[4][4][4];
#pragma unroll
    for (int mt = 0; mt < 4; mt++)
#pragma unroll
        for (int nt = 0; nt < 4; nt++)
#pragma unroll
            for (int j = 0; j < 4; j++) acc[mt][nt][j] = 0.f;

    for (int k0 = 0; k0 < Kdim; k0 += BKT) {
        // stage A and B chunk (128 rows x 16 cols each) as tf32 hi/lo
#pragma unroll
        for (int i = 0; i < 2; i++) {
            int idx = tid + i * 256;            // 0..511
            int row = idx >> 2, f4 = idx & 3;
            float4 va = *(const float4*)(A + (size_t)row * lda + k0 + f4 * 4);
            store_hilo_tf32(AsH, AsL, row, f4, va);
            float4 vb = *(const float4*)(B + (size_t)row * ldb + k0 + f4 * 4);
            store_hilo_tf32(BsH, BsL, row, f4, vb);
        }
        __syncthreads();

#pragma unroll
        for (int kg = 0; kg < 2; kg++) {
            const int woff = kg * 8 + 2 * lc;
            uint32_t bh[4][2], bl[4][2];
#pragma unroll
            for (int nt = 0; nt < 4; nt++) {
                int col = wn * 32 + nt * 8 + lr;
                uint64_t hv = *(const uint64_t*)&BsH[col * RS + woff];
                uint64_t lv = *(const uint64_t*)&BsL[col * RS + woff];
                bh[nt][0] = (uint32_t)hv; bh[nt][1] = (uint32_t)(hv >> 32);
                bl[nt][0] = (uint32_t)lv; bl[nt][1] = (uint32_t)(lv >> 32);
            }
#pragma unroll
            for (int mt = 0; mt < 4; mt++) {
                int r0 = wm * 64 + mt * 16 + lr;
                uint64_t h0 = *(const uint64_t*)&AsH[r0 * RS + woff];
                uint64_t h1 = *(const uint64_t*)&AsH[(r0 + 8) * RS + woff];
                uint64_t l0 = *(const uint64_t*)&AsL[r0 * RS + woff];
                uint64_t l1 = *(const uint64_t*)&AsL[(r0 + 8) * RS + woff];
                uint32_t ah0 = (uint32_t)h0, ah2 = (uint32_t)(h0 >> 32);
                uint32_t ah1 = (uint32_t)h1, ah3 = (uint32_t)(h1 >> 32);
                uint32_t al0 = (uint32_t)l0, al2 = (uint32_t)(l0 >> 32);
                uint32_t al1 = (uint32_t)l1, al3 = (uint32_t)(l1 >> 32);
#pragma unroll
                for (int nt = 0; nt < 4; nt++) {
                    // per-k8 chunk accumulator, drained to RN fp32 adds:
                    // keeps tensor-core accumulation chains short so any
                    // per-step accumulate rounding bias stays ~1e-6.
                    float ck[4];
                    mma_tf32_zc(ck, ah0, ah1, ah2, ah3, bh[nt][0], bh[nt][1]); // h*h
                    mma_tf32  (ck, ah0, ah1, ah2, ah3, bl[nt][0], bl[nt][1]);  // h*l
                    mma_tf32  (ck, al0, al1, al2, al3, bh[nt][0], bh[nt][1]);  // l*h
                    acc[mt][nt][0] += ck[0];
                    acc[mt][nt][1] += ck[1];
                    acc[mt][nt][2] += ck[2];
                    acc[mt][nt][3] += ck[3];
                }
            }
        }
        __syncthreads();
    }

#pragma unroll
    for (int mt = 0; mt < 4; mt++) {
        int r0 = wm * 64 + mt * 16 + lr;
#pragma unroll
        for (int nt = 0; nt < 4; nt++) {
            int cc = wn * 32 + nt * 8 + lc * 2;
            float b0v = bias ? bias[cc]     : 0.f;
            float b1v = bias ? bias[cc + 1] : 0.f;
            float* c0p = C + (size_t)r0 * ldc + cc;
            float* c1p = C + (size_t)(r0 + 8) * ldc + cc;
            *(float2*)c0p = make_float2(acc[mt][nt][0] * scale + b0v,
                                        acc[mt][nt][1] * scale + b1v);
            *(float2*)c1p = make_float2(acc[mt][nt][2] * scale + b0v,
                                        acc[mt][nt][3] * scale + b1v);
        }
    }
}

// ---------------- projection GEMM: C = A @ W^T + bias ------------------------
__global__ __launch_bounds__(256) void gemm_kernel(
    const float* __restrict__ A, const float* __restrict__ W,
    const float* __restrict__ bias, float* __restrict__ C,
    int M, int N, int K)
{
    int bm = blockIdx.y * 128, bn = blockIdx.x * 128;
    gemm_tile_tf32(A + (size_t)bm * K, K,
                   W + (size_t)bn * K, K,
                   K,
                   C + (size_t)bm * N + bn, N,
                   bias + bn, 1.f);
}

// ---------------- score GEMM: S = (Q @ K^T)/8, lower-triangular tiles --------
__global__ __launch_bounds__(256) void score_kernel(
    const float* __restrict__ Q, const float* __restrict__ Kg,
    float* __restrict__ SC)
{
    const int t = blockIdx.x;
    const int h = blockIdx.y, b = blockIdx.z;
    int qt = (int)((sqrtf(8.f * t + 1.f) - 1.f) * 0.5f);
    while ((qt + 1) * (qt + 2) / 2 <= t) qt++;
    while (qt * (qt + 1) / 2 > t) qt--;
    int kt = t - qt * (qt + 1) / 2;

    const float* Qb = Q  + (size_t)b * SEQ * DM + h * DH;
    const float* Kb = Kg + (size_t)b * SEQ * DM + h * DH;
    float* Sb = SC + (((size_t)b * NH + h) * SEQ) * SEQ;

    gemm_tile_tf32(Qb + (size_t)qt * 128 * DM, DM,
                   Kb + (size_t)kt * 128 * DM, DM,
                   DH,
                   Sb + (size_t)qt * 128 * SEQ + kt * 128, SEQ,
                   nullptr, 0.125f);
}

// ---------------- selection: streaming top-32 + softmax + AV -----------------
__global__ __launch_bounds__(256) void select_kernel(
    const float* __restrict__ SC, const float* __restrict__ Vg,
    float* __restrict__ HO, float* __restrict__ WGT, int* __restrict__ IDX)
{
    const int h = blockIdx.y, b = blockIdx.z;
    const int tid = threadIdx.x;
    const int lane = tid & 31, wid = tid >> 5;
    const int q = blockIdx.x * 8 + wid;
    const float NEG = neg_inf();

    const float* row = SC + ((((size_t)b*NH + h)*SEQ) + q) * SEQ;

    float sv = NEG;
    int   si = 0x7fffffff;

    const int nb = (q + 32) >> 5;
    for (int bi = 0; bi < nb; bi++) {
        int k = (bi << 5) + lane;
        float v = NEG; int ii = 0x7fffffff;
        if (k <= q) { v = row[k]; ii = k; }

        float minv = __shfl_sync(FULLM, sv, 31);
        int   mini = __shfl_sync(FULLM, si, 31);
        bool contend = (v > minv) || (v == minv && v != NEG && ii < mini);
        unsigned m = __ballot_sync(FULLM, contend);
        while (m) {
            int src = __ffs(m) - 1; m &= m - 1;
            float nv = __shfl_sync(FULLM, v,  src);
            int   ni = __shfl_sync(FULLM, ii, src);
            bool better = (sv > nv) || (sv == nv && si < ni);
            unsigned bm2 = __ballot_sync(FULLM, better);
            int p = __popc(bm2);
            float upv = __shfl_up_sync(FULLM, sv, 1);
            int   upi = __shfl_up_sync(FULLM, si, 1);
            if (lane == p)      { sv = nv;  si = ni;  }
            else if (lane > p)  { sv = upv; si = upi; }
        }
    }

    bool valid = (sv != NEG);
    float mx = __shfl_sync(FULLM, sv, 0);
    float e = valid ? expf(sv - mx) : 0.f;
    float tot = e;
#pragma unroll
    for (int o = 16; o; o >>= 1) tot += __shfl_xor_sync(FULLM, tot, o);
    float w = e / tot;
    int iw = valid ? si : -1;

    size_t off = ((((size_t)b*NH + h)*SEQ) + (size_t)q) * KS + lane;
    WGT[off] = w;
    IDX[off] = iw;

    const float* Vb = Vg + (size_t)b*SEQ*DM + h*DH;
    float acc0 = 0.f, acc1 = 0.f;
#pragma unroll
    for (int j = 0; j < KS; j++) {
        float wj = __shfl_sync(FULLM, w, j);
        int   ij = __shfl_sync(FULLM, iw, j);
        if (ij >= 0) {
            const float* vr = Vb + (size_t)ij * DM;
            acc0 += wj * vr[lane];
            acc1 += wj * vr[lane + 32];
        }
    }
    float* out = HO + ((size_t)(b*SEQ + q)) * DM + h*DH;
    out[lane]      = acc0;
    out[lane + 32] = acc1;
}

// ---------------- mean over heads -> dense [B, SEQ, SEQ] ---------------------
__global__ __launch_bounds__(256) void mean_kernel(
    const float* __restrict__ WGT, const int* __restrict__ IDX,
    float* __restrict__ out_attn)
{
    __shared__ float row[SEQ];
    const int q = blockIdx.x, b = blockIdx.y;
    const int tid = threadIdx.x;
    for (int i = tid; i < SEQ; i += 256) row[i] = 0.f;
    __syncthreads();
    for (int h = 0; h < NH; h++) {
        if (tid < KS) {
            size_t off = ((((size_t)b*NH + h)*SEQ) + q) * KS + tid;
            float w = WGT[off];
            int k = IDX[off];
            if (k >= 0 && w > 0.f) row[k] += w * (1.0f / NH);
        }
        __syncthreads();
    }
    float* o = out_attn + ((size_t)b*SEQ + q) * SEQ;
    for (int i = tid; i < SEQ; i += 256) o[i] = row[i];
}

// ---------------- launch -----------------------------------------------------
extern "C" void kernel_launch(void* const* d_in, const int* in_sizes, int n_in,
                              void* d_out, int out_size)
{
    const float* x  = (const float*)d_in[0];
    const float* Wq = (const float*)d_in[1];
    const float* bq = (const float*)d_in[2];
    const float* Wk = (const float*)d_in[3];
    const float* bk = (const float*)d_in[4];
    const float* Wv = (const float*)d_in[5];
    const float* bv = (const float*)d_in[6];
    const float* Wo = (const float*)d_in[7];
    const float* bo = (const float*)d_in[8];

    float *Qp, *Kp, *Vp, *HOp, *Wp, *Sp; int* Ip;
    cudaGetSymbolAddress((void**)&Qp,  g_Q);
    cudaGetSymbolAddress((void**)&Kp,  g_K);
    cudaGetSymbolAddress((void**)&Vp,  g_V);
    cudaGetSymbolAddress((void**)&HOp, g_HO);
    cudaGetSymbolAddress((void**)&Wp,  g_WGT);
    cudaGetSymbolAddress((void**)&Ip,  g_IDX);
    cudaGetSymbolAddress((void**)&Sp,  g_SC);

    dim3 ggrid(DM / 128, MROWS / 128);   // (8, 32)

    gemm_kernel<<<ggrid, 256>>>(x, Wq, bq, Qp, MROWS, DM, DM);
    gemm_kernel<<<ggrid, 256>>>(x, Wk, bk, Kp, MROWS, DM, DM);
    gemm_kernel<<<ggrid, 256>>>(x, Wv, bv, Vp, MROWS, DM, DM);

    score_kernel<<<dim3(NTRI, NH, BATCH), 256>>>(Qp, Kp, Sp);
    select_kernel<<<dim3(SEQ / 8, NH, BATCH), 256>>>(Sp, Vp, HOp, Wp, Ip);

    float* yout = (float*)d_out;
    gemm_kernel<<<ggrid, 256>>>(HOp, Wo, bo, yout, MROWS, DM, DM);

    size_t ysz = (size_t)BATCH * SEQ * DM;
    size_t asz = (size_t)BATCH * SEQ * SEQ;
    if ((size_t)out_size >= ysz + asz) {
        mean_kernel<<<dim3(SEQ, BATCH), 256>>>(Wp, Ip, (float*)d_out + ysz);
    }
}